// round 1
// baseline (speedup 1.0000x reference)
#include <cuda_runtime.h>
#include <cuda_bf16.h>
#include <cstdint>

// ---------------------------------------------------------------------------
// MTL2d_DeepSVDD: 3x (conv s2 + relu -> MHSA(relpos bias) + residual) -> pool -> linear
// B=32, heads=3, dims {16,32,64}, dh {5,10,21}, inner {15,30,63}, N {1024,256,64}
// Output: concat( z_pool (32*64), cls (32*10) ) = 2368 floats
// ---------------------------------------------------------------------------

#define BATCH 32
#define HEADS 3

// scratch (device globals; allocation-free)
__device__ float g_z1[BATCH * 16 * 32 * 32];      // 524288
__device__ float g_z2[BATCH * 32 * 16 * 16];      // 262144
__device__ float g_z3[BATCH * 64 * 8 * 8];        // 131072
__device__ float g_qkv[BATCH * 45 * 1024];        // 1474560 (max across stages)
__device__ float g_att[BATCH * 15 * 1024];        // 491520  (max across stages)

// ---------------------------------------------------------------------------
// direct 3x3 stride-2 conv, pad 1, + bias + relu
// ---------------------------------------------------------------------------
template<int CIN, int COUT, int HIN, int HOUT>
__global__ void conv_s2_relu(const float* __restrict__ x,
                             const float* __restrict__ w,
                             const float* __restrict__ bias,
                             float* __restrict__ y) {
    int idx = blockIdx.x * blockDim.x + threadIdx.x;
    constexpr int TOTAL = BATCH * COUT * HOUT * HOUT;
    if (idx >= TOTAL) return;
    int ox = idx % HOUT;
    int t  = idx / HOUT;
    int oy = t % HOUT; t /= HOUT;
    int co = t % COUT;
    int b  = t / COUT;

    float s = bias[co];
    const float* xb = x + (size_t)b * CIN * HIN * HIN;
    const float* wc = w + (size_t)co * CIN * 9;
    #pragma unroll 4
    for (int ci = 0; ci < CIN; ci++) {
        #pragma unroll
        for (int ky = 0; ky < 3; ky++) {
            int iy = oy * 2 - 1 + ky;
            if ((unsigned)iy >= (unsigned)HIN) continue;
            #pragma unroll
            for (int kx = 0; kx < 3; kx++) {
                int ix = ox * 2 - 1 + kx;
                if ((unsigned)ix >= (unsigned)HIN) continue;
                s += xb[(ci * HIN + iy) * HIN + ix] * wc[ci * 9 + ky * 3 + kx];
            }
        }
    }
    y[idx] = fmaxf(s, 0.0f);
}

// ---------------------------------------------------------------------------
// 1x1 projection: y[b,o,n] = sum_c W[o,c] * z[b,c,n] + bias[o]
// ---------------------------------------------------------------------------
template<int C, int O, int N>
__global__ void proj1x1(const float* __restrict__ z,
                        const float* __restrict__ w,
                        const float* __restrict__ bias,
                        float* __restrict__ y) {
    int idx = blockIdx.x * blockDim.x + threadIdx.x;
    constexpr int TOTAL = BATCH * O * N;
    if (idx >= TOTAL) return;
    int n = idx % N;
    int t = idx / N;
    int o = t % O;
    int b = t / O;
    float s = bias[o];
    const float* zb = z + (size_t)b * C * N;
    const float* wr = w + (size_t)o * C;
    #pragma unroll
    for (int c = 0; c < C; c++) s += wr[c] * zb[c * N + n];
    y[idx] = s;
}

// ---------------------------------------------------------------------------
// fused attention: one warp per query. scores in smem row (per warp), 2-pass
// softmax (max, then exp/sum + AV accumulate), warp-shuffle reductions.
// qkv layout (b, 3*INNER, N) with channel = dd*HEADS + h (heads fastest).
// bias = table[((yq-yk+HH-1)*(2HH-1) + (xq-xk+HH-1)) * HEADS + h], added
// BEFORE the d^-0.5 scale.
// ---------------------------------------------------------------------------
template<int N, int D, int HH>
__global__ void attn_kernel(const float* __restrict__ qkv,
                            const float* __restrict__ table,
                            float* __restrict__ o_out) {
    constexpr int INNER = 3 * D;
    constexpr int TQ = 8;                 // 8 warps = 8 queries per block
    __shared__ float sc[TQ][N];

    int bh = blockIdx.x / (N / TQ);
    int qt = blockIdx.x % (N / TQ);
    int b  = bh / HEADS;
    int h  = bh % HEADS;
    int warp = threadIdx.x >> 5;
    int lane = threadIdx.x & 31;
    int q = qt * TQ + warp;

    const float* base = qkv + (size_t)b * 3 * INNER * N;

    float qv[D];
    #pragma unroll
    for (int dd = 0; dd < D; dd++) qv[dd] = base[(dd * HEADS + h) * N + q];

    int yq = q / HH, xq = q % HH;
    const float scale = rsqrtf((float)D);

    float mx = -1e30f;
    for (int j = lane; j < N; j += 32) {
        float s = 0.0f;
        #pragma unroll
        for (int dd = 0; dd < D; dd++)
            s += qv[dd] * base[(INNER + dd * HEADS + h) * N + j];
        int yk = j / HH, xk = j % HH;
        int ridx = (yq - yk + HH - 1) * (2 * HH - 1) + (xq - xk + HH - 1);
        s = (s + table[ridx * HEADS + h]) * scale;
        sc[warp][j] = s;
        mx = fmaxf(mx, s);
    }
    #pragma unroll
    for (int off = 16; off; off >>= 1)
        mx = fmaxf(mx, __shfl_xor_sync(0xffffffffu, mx, off));

    float sum = 0.0f;
    float acc[D];
    #pragma unroll
    for (int dd = 0; dd < D; dd++) acc[dd] = 0.0f;

    for (int j = lane; j < N; j += 32) {
        float p = __expf(sc[warp][j] - mx);
        sum += p;
        #pragma unroll
        for (int dd = 0; dd < D; dd++)
            acc[dd] += p * base[(2 * INNER + dd * HEADS + h) * N + j];
    }
    #pragma unroll
    for (int off = 16; off; off >>= 1) {
        sum += __shfl_xor_sync(0xffffffffu, sum, off);
        #pragma unroll
        for (int dd = 0; dd < D; dd++)
            acc[dd] += __shfl_xor_sync(0xffffffffu, acc[dd], off);
    }

    if (lane == 0) {
        float r = 1.0f / sum;
        #pragma unroll
        for (int dd = 0; dd < D; dd++)
            o_out[((size_t)b * INNER + dd * HEADS + h) * N + q] = acc[dd] * r;
    }
}

// ---------------------------------------------------------------------------
// out projection + residual (in-place on z):
// z[b,c,n] = sum_i W[c,i] * o[b,i,n] + bias[c] + z[b,c,n]
// ---------------------------------------------------------------------------
template<int INNER, int DIM, int N>
__global__ void outproj_res(const float* __restrict__ o,
                            const float* __restrict__ w,
                            const float* __restrict__ bias,
                            float* __restrict__ z) {
    int idx = blockIdx.x * blockDim.x + threadIdx.x;
    constexpr int TOTAL = BATCH * DIM * N;
    if (idx >= TOTAL) return;
    int n = idx % N;
    int t = idx / N;
    int c = t % DIM;
    int b = t / DIM;
    float s = bias[c] + z[idx];
    const float* ob = o + (size_t)b * INNER * N;
    const float* wr = w + (size_t)c * INNER;
    #pragma unroll
    for (int i = 0; i < INNER; i++) s += wr[i] * ob[i * N + n];
    z[idx] = s;
}

// ---------------------------------------------------------------------------
// global mean pool over N=64 + classifier head. out = [z_pool(32*64) | cls(32*10)]
// ---------------------------------------------------------------------------
__global__ void pool_cls(const float* __restrict__ z3,
                         const float* __restrict__ cw,
                         const float* __restrict__ cb,
                         float* __restrict__ out) {
    int b = blockIdx.x;
    int c = threadIdx.x;   // 64 threads
    __shared__ float m[64];
    const float* zb = z3 + ((size_t)b * 64 + c) * 64;
    float s = 0.0f;
    #pragma unroll
    for (int n = 0; n < 64; n++) s += zb[n];
    s *= (1.0f / 64.0f);
    m[c] = s;
    out[b * 64 + c] = s;
    __syncthreads();
    if (c < 10) {
        float t = cb[c];
        #pragma unroll
        for (int k = 0; k < 64; k++) t += cw[c * 64 + k] * m[k];
        out[BATCH * 64 + b * 10 + c] = t;
    }
}

// ---------------------------------------------------------------------------

static inline int blocks(int total, int tpb) { return (total + tpb - 1) / tpb; }

extern "C" void kernel_launch(void* const* d_in, const int* in_sizes, int n_in,
                              void* d_out, int out_size) {
    const float* x       = (const float*)d_in[0];
    const float* conv1_w = (const float*)d_in[1];
    const float* conv1_b = (const float*)d_in[2];
    const float* qkv1_w  = (const float*)d_in[3];
    const float* qkv1_b  = (const float*)d_in[4];
    const float* out1_w  = (const float*)d_in[5];
    const float* out1_b  = (const float*)d_in[6];
    const float* rel1    = (const float*)d_in[7];
    const float* conv2_w = (const float*)d_in[8];
    const float* conv2_b = (const float*)d_in[9];
    const float* qkv2_w  = (const float*)d_in[10];
    const float* qkv2_b  = (const float*)d_in[11];
    const float* out2_w  = (const float*)d_in[12];
    const float* out2_b  = (const float*)d_in[13];
    const float* rel2    = (const float*)d_in[14];
    const float* conv3_w = (const float*)d_in[15];
    const float* conv3_b = (const float*)d_in[16];
    const float* qkv3_w  = (const float*)d_in[17];
    const float* qkv3_b  = (const float*)d_in[18];
    const float* out3_w  = (const float*)d_in[19];
    const float* out3_b  = (const float*)d_in[20];
    const float* rel3    = (const float*)d_in[21];
    const float* cls_w   = (const float*)d_in[22];
    const float* cls_b   = (const float*)d_in[23];
    float* out = (float*)d_out;

    float *z1, *z2, *z3, *qkv, *att;
    cudaGetSymbolAddress((void**)&z1,  g_z1);
    cudaGetSymbolAddress((void**)&z2,  g_z2);
    cudaGetSymbolAddress((void**)&z3,  g_z3);
    cudaGetSymbolAddress((void**)&qkv, g_qkv);
    cudaGetSymbolAddress((void**)&att, g_att);

    const int TPB = 256;

    // ---- stage 1: 64x64 -> 32x32, dim 16, N=1024, d=5, inner=15 ----
    conv_s2_relu<1, 16, 64, 32><<<blocks(BATCH*16*32*32, TPB), TPB>>>(x, conv1_w, conv1_b, z1);
    proj1x1<16, 45, 1024><<<blocks(BATCH*45*1024, TPB), TPB>>>(z1, qkv1_w, qkv1_b, qkv);
    attn_kernel<1024, 5, 32><<<BATCH*HEADS*(1024/8), 256>>>(qkv, rel1, att);
    outproj_res<15, 16, 1024><<<blocks(BATCH*16*1024, TPB), TPB>>>(att, out1_w, out1_b, z1);

    // ---- stage 2: 32x32 -> 16x16, dim 32, N=256, d=10, inner=30 ----
    conv_s2_relu<16, 32, 32, 16><<<blocks(BATCH*32*16*16, TPB), TPB>>>(z1, conv2_w, conv2_b, z2);
    proj1x1<32, 90, 256><<<blocks(BATCH*90*256, TPB), TPB>>>(z2, qkv2_w, qkv2_b, qkv);
    attn_kernel<256, 10, 16><<<BATCH*HEADS*(256/8), 256>>>(qkv, rel2, att);
    outproj_res<30, 32, 256><<<blocks(BATCH*32*256, TPB), TPB>>>(att, out2_w, out2_b, z2);

    // ---- stage 3: 16x16 -> 8x8, dim 64, N=64, d=21, inner=63 ----
    conv_s2_relu<32, 64, 16, 8><<<blocks(BATCH*64*8*8, TPB), TPB>>>(z2, conv3_w, conv3_b, z3);
    proj1x1<64, 189, 64><<<blocks(BATCH*189*64, TPB), TPB>>>(z3, qkv3_w, qkv3_b, qkv);
    attn_kernel<64, 21, 8><<<BATCH*HEADS*(64/8), 256>>>(qkv, rel3, att);
    outproj_res<63, 64, 64><<<blocks(BATCH*64*64, TPB), TPB>>>(att, out3_w, out3_b, z3);

    // ---- pool + classifier ----
    pool_cls<<<BATCH, 64>>>(z3, cls_w, cls_b, out);
}

// round 2
// speedup vs baseline: 1.5457x; 1.5457x over previous
#include <cuda_runtime.h>
#include <cuda_bf16.h>
#include <cstdint>

// ---------------------------------------------------------------------------
// MTL2d_DeepSVDD: 3x (conv s2 + relu -> MHSA(relpos bias) + residual) -> pool -> linear
// B=32, heads=3, dims {16,32,64}, dh {5,10,21}, inner {15,30,63}, N {1024,256,64}
// ---------------------------------------------------------------------------

#define BATCH 32
#define HEADS 3

__device__ float g_z1[BATCH * 16 * 32 * 32];
__device__ float g_z2[BATCH * 32 * 16 * 16];
__device__ float g_z3[BATCH * 64 * 8 * 8];
__device__ float g_qkv[BATCH * 45 * 1024];
__device__ float g_att[BATCH * 15 * 1024];

// ---------------- packed f32x2 helpers (Blackwell FFMA2 path) --------------
__device__ __forceinline__ unsigned long long pk2(float x, float y) {
    unsigned long long r;
    asm("mov.b64 %0, {%1, %2};" : "=l"(r) : "f"(x), "f"(y));
    return r;
}
__device__ __forceinline__ void upk2(unsigned long long v, float& x, float& y) {
    asm("mov.b64 {%0, %1}, %2;" : "=f"(x), "=f"(y) : "l"(v));
}
__device__ __forceinline__ unsigned long long fma2(unsigned long long a,
                                                   unsigned long long b,
                                                   unsigned long long c) {
    unsigned long long d;
    asm("fma.rn.f32x2 %0, %1, %2, %3;" : "=l"(d) : "l"(a), "l"(b), "l"(c));
    return d;
}
__device__ __forceinline__ unsigned long long mul2(unsigned long long a,
                                                   unsigned long long b) {
    unsigned long long d;
    asm("mul.rn.f32x2 %0, %1, %2;" : "=l"(d) : "l"(a), "l"(b));
    return d;
}
__device__ __forceinline__ unsigned long long add2(unsigned long long a,
                                                   unsigned long long b) {
    unsigned long long d;
    asm("add.rn.f32x2 %0, %1, %2;" : "=l"(d) : "l"(a), "l"(b));
    return d;
}

// ---------------------------------------------------------------------------
// direct 3x3 stride-2 conv, pad 1, + bias + relu
// ---------------------------------------------------------------------------
template<int CIN, int COUT, int HIN, int HOUT>
__global__ void conv_s2_relu(const float* __restrict__ x,
                             const float* __restrict__ w,
                             const float* __restrict__ bias,
                             float* __restrict__ y) {
    int idx = blockIdx.x * blockDim.x + threadIdx.x;
    constexpr int TOTAL = BATCH * COUT * HOUT * HOUT;
    if (idx >= TOTAL) return;
    int ox = idx % HOUT;
    int t  = idx / HOUT;
    int oy = t % HOUT; t /= HOUT;
    int co = t % COUT;
    int b  = t / COUT;

    float s = bias[co];
    const float* xb = x + (size_t)b * CIN * HIN * HIN;
    const float* wc = w + (size_t)co * CIN * 9;
    #pragma unroll 4
    for (int ci = 0; ci < CIN; ci++) {
        #pragma unroll
        for (int ky = 0; ky < 3; ky++) {
            int iy = oy * 2 - 1 + ky;
            if ((unsigned)iy >= (unsigned)HIN) continue;
            #pragma unroll
            for (int kx = 0; kx < 3; kx++) {
                int ix = ox * 2 - 1 + kx;
                if ((unsigned)ix >= (unsigned)HIN) continue;
                s += xb[(ci * HIN + iy) * HIN + ix] * wc[ci * 9 + ky * 3 + kx];
            }
        }
    }
    y[idx] = fmaxf(s, 0.0f);
}

// ---------------------------------------------------------------------------
// 1x1 projection
// ---------------------------------------------------------------------------
template<int C, int O, int N>
__global__ void proj1x1(const float* __restrict__ z,
                        const float* __restrict__ w,
                        const float* __restrict__ bias,
                        float* __restrict__ y) {
    int idx = blockIdx.x * blockDim.x + threadIdx.x;
    constexpr int TOTAL = BATCH * O * N;
    if (idx >= TOTAL) return;
    int n = idx % N;
    int t = idx / N;
    int o = t % O;
    int b = t / O;
    float s = bias[o];
    const float* zb = z + (size_t)b * C * N;
    const float* wr = w + (size_t)o * C;
    #pragma unroll
    for (int c = 0; c < C; c++) s += wr[c] * zb[c * N + n];
    y[idx] = s;
}

// ---------------------------------------------------------------------------
// flash attention: block = (b, h, q-slice). K,V staged in SMEM, shared by all
// warps. Each warp handles TQ queries; each lane owns j-pairs (packed f32x2).
// Online softmax with chunked rescale. Bias added BEFORE d^-0.5 scale.
// qkv layout (b, 3*INNER, N), channel = dd*HEADS + h (heads fastest).
// ---------------------------------------------------------------------------
template<int N, int D, int HH, int QBLK, int TQ>
__global__ void __launch_bounds__(256, 2)
attn_flash(const float* __restrict__ qkv,
           const float* __restrict__ table,
           float* __restrict__ o_out) {
    constexpr int INNER = 3 * D;
    constexpr int QPB = N / QBLK;             // queries per block
    constexpr int NPASS = QPB / (8 * TQ);
    constexpr int U = (N >= 128) ? 2 : 1;     // j-tiles (of 64) per chunk
    constexpr int TW = 2 * HH - 1;

    __shared__ float sk[D][N];
    __shared__ float sv[D][N];

    int qsec = blockIdx.x % QBLK;
    int bh   = blockIdx.x / QBLK;
    int b = bh / HEADS, h = bh % HEADS;
    const float* base = qkv + (size_t)b * 3 * INNER * N;

    int tid = threadIdx.x;
    // cooperative K/V load (coalesced float4)
    for (int i = tid; i < D * (N / 4); i += 256) {
        int dd = i / (N / 4);
        int j4 = i % (N / 4);
        const float4* kr = (const float4*)(base + (size_t)(INNER + dd * HEADS + h) * N);
        const float4* vr = (const float4*)(base + (size_t)(2 * INNER + dd * HEADS + h) * N);
        ((float4*)&sk[dd][0])[j4] = kr[j4];
        ((float4*)&sv[dd][0])[j4] = vr[j4];
    }
    __syncthreads();

    int warp = tid >> 5, lane = tid & 31;
    const float scale = rsqrtf((float)D);
    const float* tb = table + h;

    for (int pass = 0; pass < NPASS; pass++) {
        int q0 = qsec * QPB + (pass * 8 + warp) * TQ;

        unsigned long long qd[TQ][D];           // q duplicated in both halves
        int At[TQ];                              // per-query bias index base
        #pragma unroll
        for (int t = 0; t < TQ; t++) {
            int q = q0 + t;
            #pragma unroll
            for (int dd = 0; dd < D; dd++) {
                float qv = base[(dd * HEADS + h) * N + q];
                qd[t][dd] = pk2(qv, qv);
            }
            int yq = q / HH, xq = q % HH;
            At[t] = ((yq + HH - 1) * TW + xq + HH - 1) * HEADS;
        }

        float m[TQ], l[TQ];
        unsigned long long acc[TQ][D];
        #pragma unroll
        for (int t = 0; t < TQ; t++) {
            m[t] = -1e30f; l[t] = 0.0f;
            #pragma unroll
            for (int dd = 0; dd < D; dd++) acc[t][dd] = 0ull;
        }

        for (int c0 = 0; c0 < N; c0 += 64 * U) {
            unsigned long long s[TQ][U];
            // ---- score pass ----
            #pragma unroll
            for (int u = 0; u < U; u++) {
                int j  = c0 + u * 64 + lane * 2;
                int yk = j / HH, xk = j % HH;   // j even => j,j+1 share yk
                int off = (yk * TW + xk) * HEADS;
                unsigned long long k2[D];
                #pragma unroll
                for (int dd = 0; dd < D; dd++)
                    k2[dd] = *(const unsigned long long*)&sk[dd][j];
                #pragma unroll
                for (int t = 0; t < TQ; t++) {
                    unsigned long long sc = 0ull;
                    #pragma unroll
                    for (int dd = 0; dd < D; dd++)
                        sc = fma2(qd[t][dd], k2[dd], sc);
                    int ri = At[t] - off;
                    unsigned long long bias2 = pk2(tb[ri], tb[ri - HEADS]);
                    sc = mul2(add2(sc, bias2), pk2(scale, scale));
                    s[t][u] = sc;
                }
            }
            // ---- online max / rescale ----
            #pragma unroll
            for (int t = 0; t < TQ; t++) {
                float mx = m[t];
                #pragma unroll
                for (int u = 0; u < U; u++) {
                    float a, bb; upk2(s[t][u], a, bb);
                    mx = fmaxf(mx, fmaxf(a, bb));
                }
                if (mx > m[t]) {
                    float corr = __expf(m[t] - mx);
                    l[t] *= corr;
                    unsigned long long c2 = pk2(corr, corr);
                    #pragma unroll
                    for (int dd = 0; dd < D; dd++) acc[t][dd] = mul2(acc[t][dd], c2);
                    m[t] = mx;
                }
            }
            // ---- exp + AV pass ----
            #pragma unroll
            for (int u = 0; u < U; u++) {
                int j = c0 + u * 64 + lane * 2;
                unsigned long long v2[D];
                #pragma unroll
                for (int dd = 0; dd < D; dd++)
                    v2[dd] = *(const unsigned long long*)&sv[dd][j];
                #pragma unroll
                for (int t = 0; t < TQ; t++) {
                    float a, bb; upk2(s[t][u], a, bb);
                    float px = __expf(a - m[t]);
                    float py = __expf(bb - m[t]);
                    l[t] += px + py;
                    unsigned long long p2 = pk2(px, py);
                    #pragma unroll
                    for (int dd = 0; dd < D; dd++)
                        acc[t][dd] = fma2(p2, v2[dd], acc[t][dd]);
                }
            }
        }

        // ---- cross-lane combine & write ----
        #pragma unroll
        for (int t = 0; t < TQ; t++) {
            int q = q0 + t;
            float gm = m[t];
            #pragma unroll
            for (int off = 16; off; off >>= 1)
                gm = fmaxf(gm, __shfl_xor_sync(0xffffffffu, gm, off));
            float cf = __expf(m[t] - gm);
            float ls = l[t] * cf;
            #pragma unroll
            for (int off = 16; off; off >>= 1)
                ls += __shfl_xor_sync(0xffffffffu, ls, off);
            float inv = 1.0f / ls;
            #pragma unroll
            for (int dd = 0; dd < D; dd++) {
                float ax, ay; upk2(acc[t][dd], ax, ay);
                float a = (ax + ay) * cf;
                #pragma unroll
                for (int off = 16; off; off >>= 1)
                    a += __shfl_xor_sync(0xffffffffu, a, off);
                if (lane == 0)
                    o_out[((size_t)b * INNER + dd * HEADS + h) * N + q] = a * inv;
            }
        }
    }
}

// ---------------------------------------------------------------------------
// out projection + residual (in-place on z)
// ---------------------------------------------------------------------------
template<int INNER, int DIM, int N>
__global__ void outproj_res(const float* __restrict__ o,
                            const float* __restrict__ w,
                            const float* __restrict__ bias,
                            float* __restrict__ z) {
    int idx = blockIdx.x * blockDim.x + threadIdx.x;
    constexpr int TOTAL = BATCH * DIM * N;
    if (idx >= TOTAL) return;
    int n = idx % N;
    int t = idx / N;
    int c = t % DIM;
    int b = t / DIM;
    float s = bias[c] + z[idx];
    const float* ob = o + (size_t)b * INNER * N;
    const float* wr = w + (size_t)c * INNER;
    #pragma unroll
    for (int i = 0; i < INNER; i++) s += wr[i] * ob[i * N + n];
    z[idx] = s;
}

// ---------------------------------------------------------------------------
// mean pool + classifier
// ---------------------------------------------------------------------------
__global__ void pool_cls(const float* __restrict__ z3,
                         const float* __restrict__ cw,
                         const float* __restrict__ cb,
                         float* __restrict__ out) {
    int b = blockIdx.x;
    int c = threadIdx.x;
    __shared__ float m[64];
    const float* zb = z3 + ((size_t)b * 64 + c) * 64;
    float s = 0.0f;
    #pragma unroll
    for (int n = 0; n < 64; n++) s += zb[n];
    s *= (1.0f / 64.0f);
    m[c] = s;
    out[b * 64 + c] = s;
    __syncthreads();
    if (c < 10) {
        float t = cb[c];
        #pragma unroll
        for (int k = 0; k < 64; k++) t += cw[c * 64 + k] * m[k];
        out[BATCH * 64 + b * 10 + c] = t;
    }
}

// ---------------------------------------------------------------------------

static inline int blocks(int total, int tpb) { return (total + tpb - 1) / tpb; }

extern "C" void kernel_launch(void* const* d_in, const int* in_sizes, int n_in,
                              void* d_out, int out_size) {
    const float* x       = (const float*)d_in[0];
    const float* conv1_w = (const float*)d_in[1];
    const float* conv1_b = (const float*)d_in[2];
    const float* qkv1_w  = (const float*)d_in[3];
    const float* qkv1_b  = (const float*)d_in[4];
    const float* out1_w  = (const float*)d_in[5];
    const float* out1_b  = (const float*)d_in[6];
    const float* rel1    = (const float*)d_in[7];
    const float* conv2_w = (const float*)d_in[8];
    const float* conv2_b = (const float*)d_in[9];
    const float* qkv2_w  = (const float*)d_in[10];
    const float* qkv2_b  = (const float*)d_in[11];
    const float* out2_w  = (const float*)d_in[12];
    const float* out2_b  = (const float*)d_in[13];
    const float* rel2    = (const float*)d_in[14];
    const float* conv3_w = (const float*)d_in[15];
    const float* conv3_b = (const float*)d_in[16];
    const float* qkv3_w  = (const float*)d_in[17];
    const float* qkv3_b  = (const float*)d_in[18];
    const float* out3_w  = (const float*)d_in[19];
    const float* out3_b  = (const float*)d_in[20];
    const float* rel3    = (const float*)d_in[21];
    const float* cls_w   = (const float*)d_in[22];
    const float* cls_b   = (const float*)d_in[23];
    float* out = (float*)d_out;

    float *z1, *z2, *z3, *qkv, *att;
    cudaGetSymbolAddress((void**)&z1,  g_z1);
    cudaGetSymbolAddress((void**)&z2,  g_z2);
    cudaGetSymbolAddress((void**)&z3,  g_z3);
    cudaGetSymbolAddress((void**)&qkv, g_qkv);
    cudaGetSymbolAddress((void**)&att, g_att);

    const int TPB = 256;

    // ---- stage 1: N=1024, d=5 ----
    conv_s2_relu<1, 16, 64, 32><<<blocks(BATCH*16*32*32, TPB), TPB>>>(x, conv1_w, conv1_b, z1);
    proj1x1<16, 45, 1024><<<blocks(BATCH*45*1024, TPB), TPB>>>(z1, qkv1_w, qkv1_b, qkv);
    attn_flash<1024, 5, 32, 4, 4><<<BATCH*HEADS*4, 256>>>(qkv, rel1, att);
    outproj_res<15, 16, 1024><<<blocks(BATCH*16*1024, TPB), TPB>>>(att, out1_w, out1_b, z1);

    // ---- stage 2: N=256, d=10 ----
    conv_s2_relu<16, 32, 32, 16><<<blocks(BATCH*32*16*16, TPB), TPB>>>(z1, conv2_w, conv2_b, z2);
    proj1x1<32, 90, 256><<<blocks(BATCH*90*256, TPB), TPB>>>(z2, qkv2_w, qkv2_b, qkv);
    attn_flash<256, 10, 16, 2, 2><<<BATCH*HEADS*2, 256>>>(qkv, rel2, att);
    outproj_res<30, 32, 256><<<blocks(BATCH*32*256, TPB), TPB>>>(att, out2_w, out2_b, z2);

    // ---- stage 3: N=64, d=21 ----
    conv_s2_relu<32, 64, 16, 8><<<blocks(BATCH*64*8*8, TPB), TPB>>>(z2, conv3_w, conv3_b, z3);
    proj1x1<64, 189, 64><<<blocks(BATCH*189*64, TPB), TPB>>>(z3, qkv3_w, qkv3_b, qkv);
    attn_flash<64, 21, 8, 1, 1><<<BATCH*HEADS, 256>>>(qkv, rel3, att);
    outproj_res<63, 64, 64><<<blocks(BATCH*64*64, TPB), TPB>>>(att, out3_w, out3_b, z3);

    // ---- pool + classifier ----
    pool_cls<<<BATCH, 64>>>(z3, cls_w, cls_b, out);
}

// round 3
// speedup vs baseline: 1.7542x; 1.1349x over previous
#include <cuda_runtime.h>
#include <cuda_bf16.h>
#include <cstdint>

// ---------------------------------------------------------------------------
// MTL2d_DeepSVDD: 3x (conv s2 + relu -> MHSA(relpos bias) + residual) -> pool -> linear
// B=32, heads=3, dims {16,32,64}, dh {5,10,21}, inner {15,30,63}, N {1024,256,64}
// ---------------------------------------------------------------------------

#define BATCH 32
#define HEADS 3

__device__ float g_z1[BATCH * 16 * 32 * 32];
__device__ float g_z2[BATCH * 32 * 16 * 16];
__device__ float g_z3[BATCH * 64 * 8 * 8];
__device__ float g_qkv[BATCH * 45 * 1024];
__device__ float g_att[BATCH * 15 * 1024];

// ---------------- packed f32x2 helpers (Blackwell FFMA2 path) --------------
__device__ __forceinline__ unsigned long long pk2(float x, float y) {
    unsigned long long r;
    asm("mov.b64 %0, {%1, %2};" : "=l"(r) : "f"(x), "f"(y));
    return r;
}
__device__ __forceinline__ void upk2(unsigned long long v, float& x, float& y) {
    asm("mov.b64 {%0, %1}, %2;" : "=f"(x), "=f"(y) : "l"(v));
}
__device__ __forceinline__ unsigned long long fma2(unsigned long long a,
                                                   unsigned long long b,
                                                   unsigned long long c) {
    unsigned long long d;
    asm("fma.rn.f32x2 %0, %1, %2, %3;" : "=l"(d) : "l"(a), "l"(b), "l"(c));
    return d;
}
__device__ __forceinline__ unsigned long long mul2(unsigned long long a,
                                                   unsigned long long b) {
    unsigned long long d;
    asm("mul.rn.f32x2 %0, %1, %2;" : "=l"(d) : "l"(a), "l"(b));
    return d;
}
__device__ __forceinline__ unsigned long long add2(unsigned long long a,
                                                   unsigned long long b) {
    unsigned long long d;
    asm("add.rn.f32x2 %0, %1, %2;" : "=l"(d) : "l"(a), "l"(b));
    return d;
}
__device__ __forceinline__ float ex2f(float x) {
    float y;
    asm("ex2.approx.ftz.f32 %0, %1;" : "=f"(y) : "f"(x));
    return y;
}

// ---------------------------------------------------------------------------
// direct 3x3 stride-2 conv, pad 1, + bias + relu
// ---------------------------------------------------------------------------
template<int CIN, int COUT, int HIN, int HOUT>
__global__ void conv_s2_relu(const float* __restrict__ x,
                             const float* __restrict__ w,
                             const float* __restrict__ bias,
                             float* __restrict__ y) {
    int idx = blockIdx.x * blockDim.x + threadIdx.x;
    constexpr int TOTAL = BATCH * COUT * HOUT * HOUT;
    if (idx >= TOTAL) return;
    int ox = idx % HOUT;
    int t  = idx / HOUT;
    int oy = t % HOUT; t /= HOUT;
    int co = t % COUT;
    int b  = t / COUT;

    float s = bias[co];
    const float* xb = x + (size_t)b * CIN * HIN * HIN;
    const float* wc = w + (size_t)co * CIN * 9;
    #pragma unroll 4
    for (int ci = 0; ci < CIN; ci++) {
        #pragma unroll
        for (int ky = 0; ky < 3; ky++) {
            int iy = oy * 2 - 1 + ky;
            if ((unsigned)iy >= (unsigned)HIN) continue;
            #pragma unroll
            for (int kx = 0; kx < 3; kx++) {
                int ix = ox * 2 - 1 + kx;
                if ((unsigned)ix >= (unsigned)HIN) continue;
                s += xb[(ci * HIN + iy) * HIN + ix] * wc[ci * 9 + ky * 3 + kx];
            }
        }
    }
    y[idx] = fmaxf(s, 0.0f);
}

// ---------------------------------------------------------------------------
// 1x1 projection, float4-vectorized along n
// ---------------------------------------------------------------------------
template<int C, int O, int N>
__global__ void proj1x1(const float* __restrict__ z,
                        const float* __restrict__ w,
                        const float* __restrict__ bias,
                        float* __restrict__ y) {
    int idx = blockIdx.x * blockDim.x + threadIdx.x;
    constexpr int N4 = N / 4;
    constexpr int TOTAL4 = BATCH * O * N4;
    if (idx >= TOTAL4) return;
    int n4 = idx % N4;
    int t  = idx / N4;
    int o = t % O;
    int b = t / O;
    float bo = bias[o];
    float4 s = make_float4(bo, bo, bo, bo);
    const float4* zb = (const float4*)(z + (size_t)b * C * N);
    const float* wr = w + (size_t)o * C;
    #pragma unroll
    for (int c = 0; c < C; c++) {
        float wv = wr[c];
        float4 zv = zb[c * N4 + n4];
        s.x += wv * zv.x; s.y += wv * zv.y; s.z += wv * zv.z; s.w += wv * zv.w;
    }
    ((float4*)y)[idx] = s;
}

// ---------------------------------------------------------------------------
// flash attention: block = (b, h, q-slice). K,V + de-headed pre-scaled bias
// table staged in SMEM. Each warp handles TQ queries; each lane owns j-pairs
// (packed f32x2). Online softmax in log2 domain (q pre-scaled by scale*log2e,
// bias pre-scaled at SMEM load; exp = raw ex2.approx).
// qkv layout (b, 3*INNER, N), channel = dd*HEADS + h (heads fastest).
// ---------------------------------------------------------------------------
template<int N, int D, int HH, int QBLK, int TQ>
__global__ void __launch_bounds__(256, 2)
attn_flash(const float* __restrict__ qkv,
           const float* __restrict__ table,
           float* __restrict__ o_out) {
    constexpr int INNER = 3 * D;
    constexpr int QPB = N / QBLK;
    constexpr int NPASS = QPB / (8 * TQ);
    constexpr int U = (N >= 128) ? 2 : 1;
    constexpr int TW = 2 * HH - 1;

    __shared__ float sk[D][N];
    __shared__ float sv[D][N];
    __shared__ float st[TW * TW];        // per-head bias, pre-scaled

    int qsec = blockIdx.x % QBLK;
    int bh   = blockIdx.x / QBLK;
    int b = bh / HEADS, h = bh % HEADS;
    const float* base = qkv + (size_t)b * 3 * INNER * N;

    const float scl = rsqrtf((float)D) * 1.4426950408889634f;  // scale * log2e

    int tid = threadIdx.x;
    for (int i = tid; i < D * (N / 4); i += 256) {
        int dd = i / (N / 4);
        int j4 = i % (N / 4);
        const float4* kr = (const float4*)(base + (size_t)(INNER + dd * HEADS + h) * N);
        const float4* vr = (const float4*)(base + (size_t)(2 * INNER + dd * HEADS + h) * N);
        ((float4*)&sk[dd][0])[j4] = kr[j4];
        ((float4*)&sv[dd][0])[j4] = vr[j4];
    }
    for (int i = tid; i < TW * TW; i += 256)
        st[i] = table[i * HEADS + h] * scl;
    __syncthreads();

    int warp = tid >> 5, lane = tid & 31;

    for (int pass = 0; pass < NPASS; pass++) {
        int q0 = qsec * QPB + (pass * 8 + warp) * TQ;

        unsigned long long qd[TQ][D];
        int At[TQ];
        #pragma unroll
        for (int t = 0; t < TQ; t++) {
            int q = q0 + t;
            #pragma unroll
            for (int dd = 0; dd < D; dd++) {
                float qv = base[(dd * HEADS + h) * N + q] * scl;
                qd[t][dd] = pk2(qv, qv);
            }
            int yq = q / HH, xq = q % HH;
            At[t] = (yq + HH - 1) * TW + xq + HH - 1;
        }

        float m[TQ], l[TQ];
        unsigned long long acc[TQ][D];
        #pragma unroll
        for (int t = 0; t < TQ; t++) {
            m[t] = -1e30f; l[t] = 0.0f;
            #pragma unroll
            for (int dd = 0; dd < D; dd++) acc[t][dd] = 0ull;
        }

        for (int c0 = 0; c0 < N; c0 += 64 * U) {
            unsigned long long s[TQ][U];
            // ---- score pass ----
            #pragma unroll
            for (int u = 0; u < U; u++) {
                int j  = c0 + u * 64 + lane * 2;
                int yk = j / HH, xk = j % HH;       // even j => pair shares row
                int off = yk * TW + xk;
                unsigned long long k2[D];
                #pragma unroll
                for (int dd = 0; dd < D; dd++)
                    k2[dd] = *(const unsigned long long*)&sk[dd][j];
                #pragma unroll
                for (int t = 0; t < TQ; t++) {
                    int ri = At[t] - off;
                    unsigned long long sc = pk2(st[ri], st[ri - 1]);
                    #pragma unroll
                    for (int dd = 0; dd < D; dd++)
                        sc = fma2(qd[t][dd], k2[dd], sc);
                    s[t][u] = sc;
                }
            }
            // ---- online max / rescale ----
            #pragma unroll
            for (int t = 0; t < TQ; t++) {
                float mx = m[t];
                #pragma unroll
                for (int u = 0; u < U; u++) {
                    float a, bb; upk2(s[t][u], a, bb);
                    mx = fmaxf(mx, fmaxf(a, bb));
                }
                if (mx > m[t]) {
                    float corr = ex2f(m[t] - mx);
                    l[t] *= corr;
                    unsigned long long c2 = pk2(corr, corr);
                    #pragma unroll
                    for (int dd = 0; dd < D; dd++) acc[t][dd] = mul2(acc[t][dd], c2);
                    m[t] = mx;
                }
            }
            // ---- exp + AV pass ----
            #pragma unroll
            for (int u = 0; u < U; u++) {
                int j = c0 + u * 64 + lane * 2;
                unsigned long long v2[D];
                #pragma unroll
                for (int dd = 0; dd < D; dd++)
                    v2[dd] = *(const unsigned long long*)&sv[dd][j];
                #pragma unroll
                for (int t = 0; t < TQ; t++) {
                    float a, bb; upk2(s[t][u], a, bb);
                    float px = ex2f(a - m[t]);
                    float py = ex2f(bb - m[t]);
                    l[t] += px + py;
                    unsigned long long p2 = pk2(px, py);
                    #pragma unroll
                    for (int dd = 0; dd < D; dd++)
                        acc[t][dd] = fma2(p2, v2[dd], acc[t][dd]);
                }
            }
        }

        // ---- cross-lane combine & write ----
        #pragma unroll
        for (int t = 0; t < TQ; t++) {
            int q = q0 + t;
            float gm = m[t];
            #pragma unroll
            for (int off = 16; off; off >>= 1)
                gm = fmaxf(gm, __shfl_xor_sync(0xffffffffu, gm, off));
            float cf = ex2f(m[t] - gm);
            float ls = l[t] * cf;
            #pragma unroll
            for (int off = 16; off; off >>= 1)
                ls += __shfl_xor_sync(0xffffffffu, ls, off);
            float inv = 1.0f / ls;
            #pragma unroll
            for (int dd = 0; dd < D; dd++) {
                float ax, ay; upk2(acc[t][dd], ax, ay);
                float a = (ax + ay) * cf;
                #pragma unroll
                for (int off = 16; off; off >>= 1)
                    a += __shfl_xor_sync(0xffffffffu, a, off);
                if (lane == 0)
                    o_out[((size_t)b * INNER + dd * HEADS + h) * N + q] = a * inv;
            }
        }
    }
}

// ---------------------------------------------------------------------------
// out projection + residual (in-place on z), float4-vectorized along n
// ---------------------------------------------------------------------------
template<int INNER, int DIM, int N>
__global__ void outproj_res(const float* __restrict__ o,
                            const float* __restrict__ w,
                            const float* __restrict__ bias,
                            float* __restrict__ z) {
    int idx = blockIdx.x * blockDim.x + threadIdx.x;
    constexpr int N4 = N / 4;
    constexpr int TOTAL4 = BATCH * DIM * N4;
    if (idx >= TOTAL4) return;
    int n4 = idx % N4;
    int t  = idx / N4;
    int c = t % DIM;
    int b = t / DIM;
    float4 s = ((float4*)z)[idx];
    float bc = bias[c];
    s.x += bc; s.y += bc; s.z += bc; s.w += bc;
    const float4* ob = (const float4*)(o + (size_t)b * INNER * N);
    const float* wr = w + (size_t)c * INNER;
    #pragma unroll
    for (int i = 0; i < INNER; i++) {
        float wv = wr[i];
        float4 ov = ob[i * N4 + n4];
        s.x += wv * ov.x; s.y += wv * ov.y; s.z += wv * ov.z; s.w += wv * ov.w;
    }
    ((float4*)z)[idx] = s;
}

// ---------------------------------------------------------------------------
// mean pool + classifier
// ---------------------------------------------------------------------------
__global__ void pool_cls(const float* __restrict__ z3,
                         const float* __restrict__ cw,
                         const float* __restrict__ cb,
                         float* __restrict__ out) {
    int b = blockIdx.x;
    int c = threadIdx.x;
    __shared__ float m[64];
    const float* zb = z3 + ((size_t)b * 64 + c) * 64;
    float s = 0.0f;
    #pragma unroll
    for (int n = 0; n < 64; n++) s += zb[n];
    s *= (1.0f / 64.0f);
    m[c] = s;
    out[b * 64 + c] = s;
    __syncthreads();
    if (c < 10) {
        float t = cb[c];
        #pragma unroll
        for (int k = 0; k < 64; k++) t += cw[c * 64 + k] * m[k];
        out[BATCH * 64 + b * 10 + c] = t;
    }
}

// ---------------------------------------------------------------------------

static inline int blocks(int total, int tpb) { return (total + tpb - 1) / tpb; }

extern "C" void kernel_launch(void* const* d_in, const int* in_sizes, int n_in,
                              void* d_out, int out_size) {
    const float* x       = (const float*)d_in[0];
    const float* conv1_w = (const float*)d_in[1];
    const float* conv1_b = (const float*)d_in[2];
    const float* qkv1_w  = (const float*)d_in[3];
    const float* qkv1_b  = (const float*)d_in[4];
    const float* out1_w  = (const float*)d_in[5];
    const float* out1_b  = (const float*)d_in[6];
    const float* rel1    = (const float*)d_in[7];
    const float* conv2_w = (const float*)d_in[8];
    const float* conv2_b = (const float*)d_in[9];
    const float* qkv2_w  = (const float*)d_in[10];
    const float* qkv2_b  = (const float*)d_in[11];
    const float* out2_w  = (const float*)d_in[12];
    const float* out2_b  = (const float*)d_in[13];
    const float* rel2    = (const float*)d_in[14];
    const float* conv3_w = (const float*)d_in[15];
    const float* conv3_b = (const float*)d_in[16];
    const float* qkv3_w  = (const float*)d_in[17];
    const float* qkv3_b  = (const float*)d_in[18];
    const float* out3_w  = (const float*)d_in[19];
    const float* out3_b  = (const float*)d_in[20];
    const float* rel3    = (const float*)d_in[21];
    const float* cls_w   = (const float*)d_in[22];
    const float* cls_b   = (const float*)d_in[23];
    float* out = (float*)d_out;

    float *z1, *z2, *z3, *qkv, *att;
    cudaGetSymbolAddress((void**)&z1,  g_z1);
    cudaGetSymbolAddress((void**)&z2,  g_z2);
    cudaGetSymbolAddress((void**)&z3,  g_z3);
    cudaGetSymbolAddress((void**)&qkv, g_qkv);
    cudaGetSymbolAddress((void**)&att, g_att);

    const int TPB = 256;

    // ---- stage 1: N=1024, d=5 ----
    conv_s2_relu<1, 16, 64, 32><<<blocks(BATCH*16*32*32, TPB), TPB>>>(x, conv1_w, conv1_b, z1);
    proj1x1<16, 45, 1024><<<blocks(BATCH*45*256, TPB), TPB>>>(z1, qkv1_w, qkv1_b, qkv);
    attn_flash<1024, 5, 32, 4, 4><<<BATCH*HEADS*4, 256>>>(qkv, rel1, att);
    outproj_res<15, 16, 1024><<<blocks(BATCH*16*256, TPB), TPB>>>(att, out1_w, out1_b, z1);

    // ---- stage 2: N=256, d=10 ----
    conv_s2_relu<16, 32, 32, 16><<<blocks(BATCH*32*16*16, TPB), TPB>>>(z1, conv2_w, conv2_b, z2);
    proj1x1<32, 90, 256><<<blocks(BATCH*90*64, TPB), TPB>>>(z2, qkv2_w, qkv2_b, qkv);
    attn_flash<256, 10, 16, 2, 2><<<BATCH*HEADS*2, 256>>>(qkv, rel2, att);
    outproj_res<30, 32, 256><<<blocks(BATCH*32*64, TPB), TPB>>>(att, out2_w, out2_b, z2);

    // ---- stage 3: N=64, d=21 ----
    conv_s2_relu<32, 64, 16, 8><<<blocks(BATCH*64*8*8, TPB), TPB>>>(z2, conv3_w, conv3_b, z3);
    proj1x1<64, 189, 64><<<blocks(BATCH*189*16, TPB), TPB>>>(z3, qkv3_w, qkv3_b, qkv);
    attn_flash<64, 21, 8, 1, 1><<<BATCH*HEADS, 256>>>(qkv, rel3, att);
    outproj_res<63, 64, 64><<<blocks(BATCH*64*16, TPB), TPB>>>(att, out3_w, out3_b, z3);

    // ---- pool + classifier ----
    pool_cls<<<BATCH, 64>>>(z3, cls_w, cls_b, out);
}